// round 15
// baseline (speedup 1.0000x reference)
#include <cuda_runtime.h>
#include <cuda_fp16.h>

// OLCNN fused grouped-MLP, round 8.
// Port-bandwidth model (fits R1/R3/R5/R6): constant port ~1 B/cyc/SMSP
// (LDC.64 = 8 cyc). R3/R7's 64us == 1100 LDC.64 x 13.84 warps/SMSP x 8.
// Fix: split weight traffic across LDC and LDS ports in parallel:
//   - conv groups 0-2 (270 ulls) via __constant__  -> LDC port ~30K cyc
//   - conv groups 3-8 + hidden + middle + out (950 ulls) via smem -> LDS ~33K
//   - packed STS.64 input staging (removes ~480 LDS-port instrs/warp)
// Body otherwise identical to R3/R7 (2 elem/thread f32x2, fp16 inputs, tanh-fold).

typedef unsigned long long ull;

#define NTHREADS 128
#define ELEMS    256     // per block (2 per thread)
#define KDIM     81

// gPrep layout (ull indices):
//   [0..242]    conv W rows 0..26  (groups 0-2)      -> constant
//   [243..269]  conv b rows 0..26                    -> constant
//   [270..755]  conv W rows 27..80 (groups 3-8)      -> smem ws[0..485]
//   [756..809]  conv b rows 27..80                   -> smem ws[486..539]
//   [810..1052] Wh                                   -> smem ws[540..782]
//   [1053..1079] bh                                  -> smem ws[783..809]
//   [1080..1187] Wm                                  -> smem ws[810..917]
//   [1188..1199] bm                                  -> smem ws[918..929]
//   [1200..1215] Wo                                  -> smem ws[930..945]
//   [1216..1219] bo                                  -> smem ws[946..949]
#define NPREP  1220
#define NCONST 270
#define NWS    950

__device__   ull gPrep[NPREP];
__constant__ ull cPrep[NCONST];

__device__ __forceinline__ ull dupf(float v) {
    unsigned int b = __float_as_uint(v);
    return ((ull)b << 32) | (ull)b;
}

// Fold sigmoid(a)=0.5*tanh(a/2)+0.5 through the network (validated R2-R7).
__global__ void prep_kernel(const float* __restrict__ Wc, const float* __restrict__ bc,
                            const float* __restrict__ Wh, const float* __restrict__ bh,
                            const float* __restrict__ Wm, const float* __restrict__ bm,
                            const float* __restrict__ Wo, const float* __restrict__ bo) {
    int t = threadIdx.x;
    // conv weights: row r = g*9+k
    for (int i = t; i < 729; i += blockDim.x) {
        int r = i / 9, p = i - r * 9;
        int dst = (r < 27) ? (r * 9 + p) : (270 + (r - 27) * 9 + p);
        gPrep[dst] = dupf(0.5f * Wc[i]);
    }
    for (int r = t; r < 81; r += blockDim.x) {
        int dst = (r < 27) ? (243 + r) : (756 + (r - 27));
        gPrep[dst] = dupf(0.5f * bc[r]);
    }
    for (int i = t; i < 243; i += blockDim.x) gPrep[810 + i] = dupf(0.25f * Wh[i]);
    for (int r = t; r < 27;  r += blockDim.x) {
        float s = 0.f;
        #pragma unroll
        for (int p = 0; p < 9; p++) s += Wh[r * 9 + p];
        gPrep[1053 + r] = dupf(0.5f * bh[r] + 0.25f * s);
    }
    for (int i = t; i < 108; i += blockDim.x) gPrep[1080 + i] = dupf(0.25f * Wm[i]);
    for (int r = t; r < 12;  r += blockDim.x) {
        float s = 0.f;
        #pragma unroll
        for (int p = 0; p < 9; p++) s += Wm[r * 9 + p];
        gPrep[1188 + r] = dupf(0.5f * bm[r] + 0.25f * s);
    }
    for (int i = t; i < 16;  i += blockDim.x) gPrep[1200 + i] = dupf(0.5f * Wo[i]);
    for (int r = t; r < 4;   r += blockDim.x) {
        float s = 0.f;
        #pragma unroll
        for (int p = 0; p < 4; p++) s += Wo[r * 4 + p];
        gPrep[1216 + r] = dupf(bo[r] + 0.5f * s);
    }
}

__device__ __forceinline__ ull ffma2(ull a, ull b, ull c) {
    ull d;
    asm("fma.rn.f32x2 %0, %1, %2, %3;" : "=l"(d) : "l"(a), "l"(b), "l"(c));
    return d;
}
__device__ __forceinline__ ull pack2(float lo, float hi) {
    ull r;
    asm("mov.b64 %0, {%1, %2};" : "=l"(r) : "f"(lo), "f"(hi));
    return r;
}
__device__ __forceinline__ void unpack2(ull v, float& lo, float& hi) {
    asm("mov.b64 {%0, %1}, %2;" : "=f"(lo), "=f"(hi) : "l"(v));
}
__device__ __forceinline__ ull tanh2(ull v) {
    float lo, hi;
    unpack2(v, lo, hi);
    asm("tanh.approx.f32 %0, %0;" : "+f"(lo));
    asm("tanh.approx.f32 %0, %0;" : "+f"(hi));
    return pack2(lo, hi);
}

// weight accessors: r is a compile-time constant after full unroll,
// so the ternaries fold to a single LDC or LDS with immediate offset.
__device__ __forceinline__ ull wC(const ull* ws, int r, int p) {
    return (r < 27) ? cPrep[r * 9 + p] : ws[(r - 27) * 9 + p];
}
__device__ __forceinline__ ull bC(const ull* ws, int r) {
    return (r < 27) ? cPrep[243 + r] : ws[486 + (r - 27)];
}
#define WH(ws, r, p) ((ws)[540 + (r) * 9 + (p)])
#define BH(ws, r)    ((ws)[783 + (r)])
#define WM(ws, r, p) ((ws)[810 + (r) * 9 + (p)])
#define BM(ws, r)    ((ws)[918 + (r)])
#define WO(ws, c, p) ((ws)[930 + (c) * 4 + (p)])
#define BO(ws, c)    ((ws)[946 + (c)])

#define SMEM_BYTES (NWS * 8 + ELEMS * KDIM * 2)   // 7600 + 41472 = 49072

__global__ __launch_bounds__(NTHREADS, 4)
void olcnn_kernel(const float* __restrict__ x, float* __restrict__ out) {
    extern __shared__ ull smem_raw[];
    ull*    ws  = smem_raw;                                   // 950 ulls
    __half* s_h = reinterpret_cast<__half*>(smem_raw + NWS);  // ELEMS*KDIM halfs

    const int tid = threadIdx.x;
    const long long blk = blockIdx.x;

    // ---- stage smem-resident weights (7.6 KB, L2-hot) ----
    #pragma unroll
    for (int i = 0; i < (NWS + NTHREADS - 1) / NTHREADS; i++) {
        int idx = i * NTHREADS + tid;
        if (idx < NWS) ws[idx] = gPrep[NCONST + idx];
    }

    // ---- stage inputs: float4 -> 4 halfs packed into one STS.64 ----
    {
        const float4* __restrict__ src =
            reinterpret_cast<const float4*>(x + blk * (long long)(ELEMS * KDIM));
        for (int i = tid; i < (ELEMS * KDIM) / 4; i += NTHREADS) {
            float4 v = src[i];
            __half2 h0 = __floats2half2_rn(v.x, v.y);
            __half2 h1 = __floats2half2_rn(v.z, v.w);
            union { uint2 u; __half2 h[2]; } tmp;
            tmp.h[0] = h0; tmp.h[1] = h1;
            *reinterpret_cast<uint2*>(s_h + i * 4) = tmp.u;
        }
    }
    __syncthreads();

    // thread handles elements e0=tid, e1=tid+128
    const __half* __restrict__ xa = s_h + tid * KDIM;
    const __half* __restrict__ xb = s_h + (tid + NTHREADS) * KDIM;

    ull lg[4];
    #pragma unroll
    for (int c = 0; c < 4; c++) lg[c] = BO(ws, c);

    #pragma unroll
    for (int G = 0; G < 3; G++) {
        ull h[9];

        #pragma unroll
        for (int s = 0; s < 3; s++) {
            const int g  = 3 * G + s;
            const int gr = g / 3, gc = g % 3;

            ull px[9];
            #pragma unroll
            for (int p = 0; p < 9; p++) {
                const int k = (3 * gr + p / 3) * 9 + (3 * gc + p % 3);
                px[p] = pack2(__half2float(xa[k]), __half2float(xb[k]));
            }

            // conv: 9 kernels -> tanh  (rows 0..26 from LDC, 27..80 from LDS)
            ull f[9];
            #pragma unroll
            for (int k = 0; k < 9; k++) {
                const int r = g * 9 + k;
                ull acc = bC(ws, r);
                #pragma unroll
                for (int p = 0; p < 9; p++)
                    acc = ffma2(px[p], wC(ws, r, p), acc);
                f[k] = tanh2(acc);
            }

            // hidden: 3 neurons -> tanh (smem)
            #pragma unroll
            for (int n = 0; n < 3; n++) {
                const int r = g * 3 + n;
                ull acc = BH(ws, r);
                #pragma unroll
                for (int k = 0; k < 9; k++)
                    acc = ffma2(f[k], WH(ws, r, k), acc);
                h[s * 3 + n] = tanh2(acc);
            }
        }

        // middle group G: 4 neurons -> tanh -> fold into logits (smem)
        #pragma unroll
        for (int n = 0; n < 4; n++) {
            const int r = G * 4 + n;
            ull acc = BM(ws, r);
            #pragma unroll
            for (int p = 0; p < 9; p++)
                acc = ffma2(h[p], WM(ws, r, p), acc);
            ull mv = tanh2(acc);

            lg[G] = ffma2(mv, WO(ws, G, n), lg[G]);
            if (G == 0)
                lg[3] = ffma2(mv, WO(ws, 3, n), lg[3]);
        }
    }

    float lo[4], hi[4];
    #pragma unroll
    for (int c = 0; c < 4; c++) unpack2(lg[c], lo[c], hi[c]);

    float4* __restrict__ o4 = reinterpret_cast<float4*>(out) + blk * ELEMS;
    o4[tid]            = make_float4(lo[0], lo[1], lo[2], lo[3]);
    o4[tid + NTHREADS] = make_float4(hi[0], hi[1], hi[2], hi[3]);
}

extern "C" void kernel_launch(void* const* d_in, const int* in_sizes, int n_in,
                              void* d_out, int out_size) {
    const float* x = (const float*)d_in[0];

    prep_kernel<<<1, 256>>>((const float*)d_in[1], (const float*)d_in[2],
                            (const float*)d_in[3], (const float*)d_in[4],
                            (const float*)d_in[5], (const float*)d_in[6],
                            (const float*)d_in[7], (const float*)d_in[8]);
    void* gptr = nullptr;
    cudaGetSymbolAddress(&gptr, gPrep);
    cudaMemcpyToSymbolAsync(cPrep, gptr, NCONST * sizeof(ull), 0,
                            cudaMemcpyDeviceToDevice, 0);

    const int B = in_sizes[0] / KDIM;        // 524288
    const int nblocks = B / ELEMS;           // 2048

    cudaFuncSetAttribute(olcnn_kernel, cudaFuncAttributeMaxDynamicSharedMemorySize,
                         SMEM_BYTES);
    cudaFuncSetAttribute(olcnn_kernel, cudaFuncAttributePreferredSharedMemoryCarveout, 100);

    olcnn_kernel<<<nblocks, NTHREADS, SMEM_BYTES>>>(x, (float*)d_out);
}

// round 17
// speedup vs baseline: 1.0176x; 1.0176x over previous
#include <cuda_runtime.h>
#include <cuda_fp16.h>

// OLCNN fused grouped-MLP, round 9.
// Hypothesis under test: constant port is TRANSACTION-limited (~8 cyc/LDC
// regardless of width). If true, LDC.128 (ulonglong2 rows [w0..w8,b]) halves
// the dominant port cost (1216 -> ~630 LDC/warp).
// Also: 2-chain accumulators per dot (chain 36 -> ~24 cyc) for latency cover.
// Body otherwise = proven R3/R7 (64us): 2 elem/thread f32x2, fp16 e-major smem
// inputs, packed STS.64 staging, folded-tanh network.

typedef unsigned long long ull;

#define NTHREADS 128
#define ELEMS    256     // per block (2 per thread)
#define KDIM     81

// blob layout (ull units), every row 16B-aligned:
//   conv   row r (r=0..80):  [r*10 .. r*10+8]=W, [r*10+9]=bias
//   hidden row r (r=0..26):  base 810
//   middle row r (r=0..11):  base 1080
//   out    row c (c=0..3):   base 1200, stride 6: [w0..w3, bias, pad]
#define NPREP 1224

__device__   ull gPrep[NPREP];
__constant__ ull cPrep[NPREP];   // 9.8 KB

__device__ __forceinline__ ull dupf(float v) {
    unsigned int b = __float_as_uint(v);
    return ((ull)b << 32) | (ull)b;
}

// Fold sigmoid(a)=0.5*tanh(a/2)+0.5 through the network (validated R2-R8).
__global__ void prep_kernel(const float* __restrict__ Wc, const float* __restrict__ bc,
                            const float* __restrict__ Wh, const float* __restrict__ bh,
                            const float* __restrict__ Wm, const float* __restrict__ bm,
                            const float* __restrict__ Wo, const float* __restrict__ bo) {
    int t = threadIdx.x;
    for (int r = t; r < 81; r += blockDim.x) {
        #pragma unroll
        for (int p = 0; p < 9; p++)
            gPrep[r * 10 + p] = dupf(0.5f * Wc[r * 9 + p]);
        gPrep[r * 10 + 9] = dupf(0.5f * bc[r]);
    }
    for (int r = t; r < 27; r += blockDim.x) {
        float s = 0.f;
        #pragma unroll
        for (int p = 0; p < 9; p++) {
            s += Wh[r * 9 + p];
            gPrep[810 + r * 10 + p] = dupf(0.25f * Wh[r * 9 + p]);
        }
        gPrep[810 + r * 10 + 9] = dupf(0.5f * bh[r] + 0.25f * s);
    }
    for (int r = t; r < 12; r += blockDim.x) {
        float s = 0.f;
        #pragma unroll
        for (int p = 0; p < 9; p++) {
            s += Wm[r * 9 + p];
            gPrep[1080 + r * 10 + p] = dupf(0.25f * Wm[r * 9 + p]);
        }
        gPrep[1080 + r * 10 + 9] = dupf(0.5f * bm[r] + 0.25f * s);
    }
    for (int r = t; r < 4; r += blockDim.x) {
        float s = 0.f;
        #pragma unroll
        for (int p = 0; p < 4; p++) {
            s += Wo[r * 4 + p];
            gPrep[1200 + r * 6 + p] = dupf(0.5f * Wo[r * 4 + p]);
        }
        gPrep[1200 + r * 6 + 4] = dupf(bo[r] + 0.5f * s);
        gPrep[1200 + r * 6 + 5] = 0ull;
    }
}

__device__ __forceinline__ ull ffma2(ull a, ull b, ull c) {
    ull d;
    asm("fma.rn.f32x2 %0, %1, %2, %3;" : "=l"(d) : "l"(a), "l"(b), "l"(c));
    return d;
}
__device__ __forceinline__ ull fmul2(ull a, ull b) {
    ull d;
    asm("mul.rn.f32x2 %0, %1, %2;" : "=l"(d) : "l"(a), "l"(b));
    return d;
}
__device__ __forceinline__ ull fadd2(ull a, ull b) {
    ull d;
    asm("add.rn.f32x2 %0, %1, %2;" : "=l"(d) : "l"(a), "l"(b));
    return d;
}
__device__ __forceinline__ ull pack2(float lo, float hi) {
    ull r;
    asm("mov.b64 %0, {%1, %2};" : "=l"(r) : "f"(lo), "f"(hi));
    return r;
}
__device__ __forceinline__ void unpack2(ull v, float& lo, float& hi) {
    asm("mov.b64 {%0, %1}, %2;" : "=f"(lo), "=f"(hi) : "l"(v));
}
__device__ __forceinline__ ull tanh2(ull v) {
    float lo, hi;
    unpack2(v, lo, hi);
    asm("tanh.approx.f32 %0, %0;" : "+f"(lo));
    asm("tanh.approx.f32 %0, %0;" : "+f"(hi));
    return pack2(lo, hi);
}

// 9-dot + bias from a 10-ull row: 5x LDC.128, two accumulator chains.
// row2 = cPrep viewed as ulonglong2, base = row_ull/2 (rows are 16B-aligned).
__device__ __forceinline__ ull dot9(const ulonglong2* __restrict__ r2,
                                    const ull* __restrict__ v) {
    ulonglong2 w01 = r2[0];
    ulonglong2 w23 = r2[1];
    ulonglong2 w45 = r2[2];
    ulonglong2 w67 = r2[3];
    ulonglong2 w8b = r2[4];        // {w8, bias}
    // even chain (5 fma, seeded by bias), odd chain (1 mul + 3 fma)
    ull a0 = ffma2(v[0], w01.x, w8b.y);
    ull a1 = fmul2(v[1], w01.y);
    a0 = ffma2(v[2], w23.x, a0);
    a1 = ffma2(v[3], w23.y, a1);
    a0 = ffma2(v[4], w45.x, a0);
    a1 = ffma2(v[5], w45.y, a1);
    a0 = ffma2(v[6], w67.x, a0);
    a1 = ffma2(v[7], w67.y, a1);
    a0 = ffma2(v[8], w8b.x, a0);
    return fadd2(a0, a1);
}

__global__ __launch_bounds__(NTHREADS, 5)
void olcnn_kernel(const float* __restrict__ x, float* __restrict__ out) {
    extern __shared__ __half s_h[];   // ELEMS*KDIM halfs = 41472 B, element-major

    const int tid = threadIdx.x;
    const long long blk = blockIdx.x;

    // ---- stage inputs: float4 -> 4 halfs packed into one STS.64 ----
    {
        const float4* __restrict__ src =
            reinterpret_cast<const float4*>(x + blk * (long long)(ELEMS * KDIM));
        for (int i = tid; i < (ELEMS * KDIM) / 4; i += NTHREADS) {
            float4 v = src[i];
            __half2 h0 = __floats2half2_rn(v.x, v.y);
            __half2 h1 = __floats2half2_rn(v.z, v.w);
            union { uint2 u; __half2 h[2]; } tmp;
            tmp.h[0] = h0; tmp.h[1] = h1;
            *reinterpret_cast<uint2*>(s_h + i * 4) = tmp.u;
        }
    }
    __syncthreads();

    const __half* __restrict__ xa = s_h + tid * KDIM;
    const __half* __restrict__ xb = s_h + (tid + NTHREADS) * KDIM;

    const ulonglong2* __restrict__ C2 = reinterpret_cast<const ulonglong2*>(cPrep);

    ull lg[4];
    #pragma unroll
    for (int c = 0; c < 4; c++) lg[c] = cPrep[1200 + c * 6 + 4];   // bo'

    #pragma unroll
    for (int G = 0; G < 3; G++) {
        ull h[9];

        #pragma unroll
        for (int s = 0; s < 3; s++) {
            const int g  = 3 * G + s;
            const int gr = g / 3, gc = g % 3;

            ull px[9];
            #pragma unroll
            for (int p = 0; p < 9; p++) {
                const int k = (3 * gr + p / 3) * 9 + (3 * gc + p % 3);
                px[p] = pack2(__half2float(xa[k]), __half2float(xb[k]));
            }

            // conv: 9 kernels -> tanh
            ull f[9];
            #pragma unroll
            for (int k = 0; k < 9; k++)
                f[k] = tanh2(dot9(C2 + (g * 9 + k) * 5, px));

            // hidden: 3 neurons -> tanh
            #pragma unroll
            for (int n = 0; n < 3; n++)
                h[s * 3 + n] = tanh2(dot9(C2 + 405 + (g * 3 + n) * 5, f));
        }

        // middle group G: 4 neurons -> tanh -> fold into logits
        #pragma unroll
        for (int n = 0; n < 4; n++) {
            ull mv = tanh2(dot9(C2 + 540 + (G * 4 + n) * 5, h));

            lg[G] = ffma2(mv, cPrep[1200 + G * 6 + n], lg[G]);
            if (G == 0)
                lg[3] = ffma2(mv, cPrep[1200 + 3 * 6 + n], lg[3]);
        }
    }

    float lo[4], hi[4];
    #pragma unroll
    for (int c = 0; c < 4; c++) unpack2(lg[c], lo[c], hi[c]);

    float4* __restrict__ o4 = reinterpret_cast<float4*>(out) + blk * ELEMS;
    o4[tid]            = make_float4(lo[0], lo[1], lo[2], lo[3]);
    o4[tid + NTHREADS] = make_float4(hi[0], hi[1], hi[2], hi[3]);
}

extern "C" void kernel_launch(void* const* d_in, const int* in_sizes, int n_in,
                              void* d_out, int out_size) {
    const float* x = (const float*)d_in[0];

    prep_kernel<<<1, 256>>>((const float*)d_in[1], (const float*)d_in[2],
                            (const float*)d_in[3], (const float*)d_in[4],
                            (const float*)d_in[5], (const float*)d_in[6],
                            (const float*)d_in[7], (const float*)d_in[8]);
    void* gptr = nullptr;
    cudaGetSymbolAddress(&gptr, gPrep);
    cudaMemcpyToSymbolAsync(cPrep, gptr, NPREP * sizeof(ull), 0,
                            cudaMemcpyDeviceToDevice, 0);

    const int B = in_sizes[0] / KDIM;        // 524288
    const int nblocks = B / ELEMS;           // 2048

    const int smem = ELEMS * KDIM * (int)sizeof(__half);   // 41472 B
    cudaFuncSetAttribute(olcnn_kernel, cudaFuncAttributeMaxDynamicSharedMemorySize, smem);
    cudaFuncSetAttribute(olcnn_kernel, cudaFuncAttributePreferredSharedMemoryCarveout, 100);

    olcnn_kernel<<<nblocks, NTHREADS, smem>>>(x, (float*)d_out);
}